// round 2
// baseline (speedup 1.0000x reference)
#include <cuda_runtime.h>

#define N_NODES 20000
#define F_DIM   4
#define T_DIM   12
#define C_DIM   256
#define FT      48          // F*T
#define ER_E    30000
#define HID_D   128
#define OUT_D   12
#define NREG    5
#define NPB     32          // nodes per block in main kernel

// ---------------- device scratch (no allocations allowed) ----------------
__device__ float g_dinv[NREG * N_NODES];   // deg, converted to rsqrt(deg) in place
__device__ float g_selfc[N_NODES];         // sum_r 1/deg_r
__device__ float g_AX[N_NODES * FT];       // aggregated x, layout [n][f][t]
__device__ float g_Mz[F_DIM * C_DIM];
__device__ float g_Mh[F_DIM * C_DIM];
__device__ float g_bz[C_DIM];
__device__ float g_bh[C_DIM];
__device__ float g_probs[T_DIM];

struct RegPtrs { const int* idx[NREG]; const float* w[NREG]; };

// ---------------- kernels ----------------
__global__ void k_init_deg() {
    int i = blockIdx.x * blockDim.x + threadIdx.x;
    if (i < NREG * N_NODES) g_dinv[i] = 1.0f;   // self-loop contributes 1
}

__global__ void k_deg(RegPtrs rp) {
    int e = blockIdx.x * blockDim.x + threadIdx.x;
    int r = blockIdx.y;
    if (e < ER_E) {
        int dst = rp.idx[r][ER_E + e];
        atomicAdd(&g_dinv[r * N_NODES + dst], rp.w[r][e]);
    }
}

__global__ void k_dinv() {
    int i = blockIdx.x * blockDim.x + threadIdx.x;
    if (i < N_NODES) {
        float s = 0.f;
#pragma unroll
        for (int r = 0; r < NREG; r++) {
            float d = g_dinv[r * N_NODES + i];
            g_dinv[r * N_NODES + i] = rsqrtf(d);
            s += __fdividef(1.0f, d);
        }
        g_selfc[i] = s;
    }
}

__global__ void k_ax_self(const float* __restrict__ x) {
    int i = blockIdx.x * blockDim.x + threadIdx.x;
    if (i < N_NODES * FT) g_AX[i] = g_selfc[i / FT] * x[i];
}

// one warp per edge: gather 48 floats from x[src], atomicAdd into AX[dst]
__global__ void k_scatter(RegPtrs rp, const float* __restrict__ x) {
    int warp = (blockIdx.x * blockDim.x + threadIdx.x) >> 5;
    int lane = threadIdx.x & 31;
    int r = blockIdx.y;
    if (warp >= ER_E) return;
    const int* idx = rp.idx[r];
    int src = idx[warp];
    int dst = idx[ER_E + warp];
    float coef = g_dinv[r * N_NODES + src] * rp.w[r][warp] * g_dinv[r * N_NODES + dst];
    const float* xs = x + (size_t)src * FT;
    float* ax = g_AX + (size_t)dst * FT;
    atomicAdd(&ax[lane], coef * xs[lane]);
    if (lane < 16) atomicAdd(&ax[32 + lane], coef * xs[32 + lane]);
}

// M = Wc @ Wl[:C], b' = bc @ Wl[:C] + bl  (both gates); softmax(attention)
__global__ void k_precompute(const float* __restrict__ Wc_z, const float* __restrict__ bc_z,
                             const float* __restrict__ Wl_z, const float* __restrict__ bl_z,
                             const float* __restrict__ Wc_h, const float* __restrict__ bc_h,
                             const float* __restrict__ Wl_h, const float* __restrict__ bl_h,
                             const float* __restrict__ attention) {
    __shared__ float sWcz[F_DIM * C_DIM], sWch[F_DIM * C_DIM];
    __shared__ float sbcz[C_DIM], sbch[C_DIM];
    int tid = threadIdx.x;  // 256 threads
    for (int i = tid; i < F_DIM * C_DIM; i += 256) { sWcz[i] = Wc_z[i]; sWch[i] = Wc_h[i]; }
    sbcz[tid] = bc_z[tid];
    sbch[tid] = bc_h[tid];
    __syncthreads();
    float mz[F_DIM] = {0, 0, 0, 0}, mh[F_DIM] = {0, 0, 0, 0}, bz = 0.f, bh = 0.f;
    for (int k = 0; k < C_DIM; k++) {
        float wz = Wl_z[k * C_DIM + tid];
        float wh = Wl_h[k * C_DIM + tid];
#pragma unroll
        for (int f = 0; f < F_DIM; f++) {
            mz[f] = fmaf(sWcz[f * C_DIM + k], wz, mz[f]);
            mh[f] = fmaf(sWch[f * C_DIM + k], wh, mh[f]);
        }
        bz = fmaf(sbcz[k], wz, bz);
        bh = fmaf(sbch[k], wh, bh);
    }
#pragma unroll
    for (int f = 0; f < F_DIM; f++) {
        g_Mz[f * C_DIM + tid] = mz[f];
        g_Mh[f * C_DIM + tid] = mh[f];
    }
    g_bz[tid] = bz + bl_z[tid];
    g_bh[tid] = bh + bl_h[tid];
    if (tid == 0) {
        float mx = -1e30f;
        for (int t = 0; t < T_DIM; t++) mx = fmaxf(mx, attention[t]);
        float p[T_DIM], s = 0.f;
        for (int t = 0; t < T_DIM; t++) { p[t] = __expf(attention[t] - mx); s += p[t]; }
        float is = __fdividef(1.0f, s);
        for (int t = 0; t < T_DIM; t++) g_probs[t] = p[t] * is;
    }
}

// fused: gates -> attention pooling -> h out -> relu -> MLP(256->128->12) -> y out
// SMEM layout (floats): W1 32768 | W2 1536 | Mz 1024 | Mh 1024 | bz 256 | bh 256 |
//                       b1 128 | b2 16 | probs 16 | AX 1536 | h 8192 | y1 4096 = 50848
#define SMEM_FLOATS 50848
#define SMEM_BYTES  (SMEM_FLOATS * 4)

__global__ void __launch_bounds__(256, 1)
k_main(const float* __restrict__ W1, const float* __restrict__ b1,
       const float* __restrict__ W2, const float* __restrict__ b2,
       float* __restrict__ out_y, float* __restrict__ out_h, int write_h) {
    extern __shared__ float sm[];
    float* W1s = sm;                 // 32768
    float* W2s = W1s + 32768;        // 1536
    float* Mzs = W2s + 1536;         // 1024
    float* Mhs = Mzs + 1024;         // 1024
    float* bzs = Mhs + 1024;         // 256
    float* bhs = bzs + 256;          // 256
    float* b1s = bhs + 256;          // 128
    float* b2s = b1s + 128;          // 16
    float* prs = b2s + 16;           // 16
    float* AXs = prs + 16;           // 1536
    float* hs  = AXs + 1536;         // 8192
    float* y1s = hs + 8192;          // 4096

    int tid = threadIdx.x;
    for (int i = tid; i < 32768; i += 256) W1s[i] = W1[i];
    for (int i = tid; i < 1536; i += 256) W2s[i] = W2[i];
    for (int i = tid; i < 1024; i += 256) { Mzs[i] = g_Mz[i]; Mhs[i] = g_Mh[i]; }
    bzs[tid] = g_bz[tid];
    bhs[tid] = g_bh[tid];
    if (tid < HID_D) b1s[tid] = b1[tid];
    if (tid < OUT_D) b2s[tid] = b2[tid];
    if (tid < T_DIM) prs[tid] = g_probs[tid];
    int base = blockIdx.x * NPB;
    for (int i = tid; i < NPB * FT; i += 256) AXs[i] = g_AX[base * FT + i];
    __syncthreads();

    // ---- gate phase: thread = channel c ----
    int c = tid;
    float mz0 = Mzs[c], mz1 = Mzs[256 + c], mz2 = Mzs[512 + c], mz3 = Mzs[768 + c];
    float mh0 = Mhs[c], mh1 = Mhs[256 + c], mh2 = Mhs[512 + c], mh3 = Mhs[768 + c];
    float bz = bzs[c], bh = bhs[c];
    for (int ln = 0; ln < NPB; ln++) {
        const float* ax = AXs + ln * FT;   // [f][t]
        float acc = 0.f;
#pragma unroll
        for (int t = 0; t < T_DIM; t++) {
            float a0 = ax[t], a1 = ax[12 + t], a2 = ax[24 + t], a3 = ax[36 + t];
            float az = fmaf(a3, mz3, fmaf(a2, mz2, fmaf(a1, mz1, fmaf(a0, mz0, bz))));
            float ah = fmaf(a3, mh3, fmaf(a2, mh2, fmaf(a1, mh1, fmaf(a0, mh0, bh))));
            // (1 - sigmoid(az)) = 1/(1+e^az) ; tanh(ah) = 1 - 2/(e^{2ah}+1)
            float ez = __expf(az);
            float s  = __fdividef(1.0f, 1.0f + ez);
            float e2 = __expf(2.0f * ah);
            float th = 1.0f - __fdividef(2.0f, e2 + 1.0f);
            acc = fmaf(prs[t] * s, th, acc);
        }
        if (write_h) out_h[(base + ln) * C_DIM + c] = acc;   // raw h output
        hs[ln * C_DIM + c] = fmaxf(acc, 0.f);                 // relu(h) for MLP
    }
    __syncthreads();

    // ---- MLP layer 1: 32 nodes x 128 outputs; thread (half, j) does 16 nodes ----
    int j = tid & 127;
    int half = tid >> 7;
    float acc1[16];
#pragma unroll
    for (int i = 0; i < 16; i++) acc1[i] = b1s[j];
    const float* hrow = hs + half * 16 * C_DIM;
    for (int k = 0; k < C_DIM; k++) {
        float w = W1s[k * HID_D + j];
#pragma unroll
        for (int i = 0; i < 16; i++) acc1[i] = fmaf(hrow[i * C_DIM + k], w, acc1[i]);
    }
#pragma unroll
    for (int i = 0; i < 16; i++) y1s[(half * 16 + i) * HID_D + j] = fmaxf(acc1[i], 0.f);
    __syncthreads();

    // ---- MLP layer 2: 32 nodes x 12 outputs ----
    for (int o = tid; o < NPB * OUT_D; o += 256) {
        int ln = o / OUT_D, oo = o - ln * OUT_D;
        float s = b2s[oo];
        const float* yr = y1s + ln * HID_D;
#pragma unroll 16
        for (int jj = 0; jj < HID_D; jj++) s = fmaf(yr[jj], W2s[jj * OUT_D + oo], s);
        out_y[(base + ln) * OUT_D + oo] = s;
    }
}

// ---------------- launch ----------------
extern "C" void kernel_launch(void* const* d_in, const int* in_sizes, int n_in,
                              void* d_out, int out_size) {
    (void)in_sizes; (void)n_in;
    const float* x = (const float*)d_in[0];
    // d_in[1] = full-graph edge_index: provably unused by the reference
    RegPtrs rp;
    for (int r = 0; r < NREG; r++) {
        rp.idx[r] = (const int*)d_in[2 + r];
        rp.w[r]   = (const float*)d_in[7 + r];
    }
    const float* Wc_z = (const float*)d_in[12];
    const float* bc_z = (const float*)d_in[13];
    const float* Wl_z = (const float*)d_in[14];
    const float* bl_z = (const float*)d_in[15];
    // d_in[16..19] = reset-gate params: cannot influence output (H0 = 0)
    const float* Wc_h = (const float*)d_in[20];
    const float* bc_h = (const float*)d_in[21];
    const float* Wl_h = (const float*)d_in[22];
    const float* bl_h = (const float*)d_in[23];
    const float* att  = (const float*)d_in[24];
    const float* W1   = (const float*)d_in[25];
    const float* b1   = (const float*)d_in[26];
    const float* W2   = (const float*)d_in[27];
    const float* b2   = (const float*)d_in[28];

    float* out   = (float*)d_out;
    float* out_y = out;
    int write_h  = (out_size >= N_NODES * (OUT_D + C_DIM)) ? 1 : 0;
    float* out_h = out + N_NODES * OUT_D;

    k_init_deg<<<(NREG * N_NODES + 255) / 256, 256>>>();
    dim3 gdeg((ER_E + 255) / 256, NREG);
    k_deg<<<gdeg, 256>>>(rp);
    k_dinv<<<(N_NODES + 255) / 256, 256>>>();
    k_ax_self<<<(N_NODES * FT + 255) / 256, 256>>>(x);
    dim3 gsc((ER_E + 7) / 8, NREG);   // 8 warps/block, 1 warp per edge
    k_scatter<<<gsc, 256>>>(rp, x);
    k_precompute<<<1, 256>>>(Wc_z, bc_z, Wl_z, bl_z, Wc_h, bc_h, Wl_h, bl_h, att);

    cudaFuncSetAttribute(k_main, cudaFuncAttributeMaxDynamicSharedMemorySize, SMEM_BYTES);
    k_main<<<N_NODES / NPB, 256, SMEM_BYTES>>>(W1, b1, W2, b2, out_y, out_h, write_h);
}